// round 1
// baseline (speedup 1.0000x reference)
#include <cuda_runtime.h>
#include <math.h>

#define BT_N 64      // b*t
#define LQ   256
#define LK   512
#define CDIM 512
#define NH   8
#define HD   64

// scratch (device globals are the sanctioned scratch mechanism)
__device__ float g_qh[(size_t)BT_N * NH * LQ * HD];   // 33.5 MB
__device__ float g_kh[(size_t)BT_N * NH * LK * HD];   // 67 MB
__device__ float g_vh[(size_t)BT_N * NH * LK * HD];   // 67 MB
__device__ float g_xm[(size_t)BT_N * LQ * CDIM];      // 33.5 MB (merged-head attention out)

// ---------------------------------------------------------------------------
// GEMM: out[m][n] = sum_k A[m][k] * W[n][k] + bias[n]   (NT, K = 512)
// Tile: BM=128, BN=64, BK=16, 256 threads (16x16), per-thread 8x4.
// MODE 0: A=q (M=16384),  epilogue: L2-normalize 64-chunk, store g_qh
// MODE 1: A=kv (M=32768), epilogue: normalize, store g_kh (cols<512) / g_vh
// MODE 2: A=g_xm (M=16384), epilogue: + bias + shortcut -> out
// ---------------------------------------------------------------------------
template<int MODE>
__global__ __launch_bounds__(256)
void gemm_kernel(const float* __restrict__ A,
                 const float* __restrict__ W,
                 const float* __restrict__ bias,
                 const float* __restrict__ shortcut,
                 float* __restrict__ out)
{
    __shared__ float As[16][132];
    __shared__ float Bs[16][68];

    const int tid = threadIdx.x;
    const int tx  = tid & 15;
    const int ty  = tid >> 4;
    const int bm  = blockIdx.y * 128;
    const int bn  = blockIdx.x * 64;
    const int K   = CDIM;

    const float* Ap = (MODE == 2) ? (const float*)g_xm : A;
    const float* Ab = Ap + (size_t)bm * K;
    const float* Wb = W  + (size_t)bn * K;

    float acc[8][4];
    #pragma unroll
    for (int i = 0; i < 8; i++)
        #pragma unroll
        for (int j = 0; j < 4; j++) acc[i][j] = 0.f;

    for (int kt = 0; kt < K; kt += 16) {
        // A tile: 128 rows x 16 k  (store transposed As[k][m])
        #pragma unroll
        for (int l = 0; l < 2; l++) {
            int idx = tid + l * 256;
            int m = idx >> 2;
            int c = (idx & 3) * 4;
            float4 v = *(const float4*)(Ab + (size_t)m * K + kt + c);
            As[c + 0][m] = v.x;
            As[c + 1][m] = v.y;
            As[c + 2][m] = v.z;
            As[c + 3][m] = v.w;
        }
        // B tile: 64 rows x 16 k (store Bs[k][n])
        {
            int n = tid >> 2;
            int c = (tid & 3) * 4;
            float4 v = *(const float4*)(Wb + (size_t)n * K + kt + c);
            Bs[c + 0][n] = v.x;
            Bs[c + 1][n] = v.y;
            Bs[c + 2][n] = v.z;
            Bs[c + 3][n] = v.w;
        }
        __syncthreads();
        #pragma unroll
        for (int k = 0; k < 16; k++) {
            float4 a0 = *(const float4*)&As[k][ty * 8];
            float4 a1 = *(const float4*)&As[k][ty * 8 + 4];
            float4 b0 = *(const float4*)&Bs[k][tx * 4];
            float a[8] = {a0.x, a0.y, a0.z, a0.w, a1.x, a1.y, a1.z, a1.w};
            float b[4] = {b0.x, b0.y, b0.z, b0.w};
            #pragma unroll
            for (int i = 0; i < 8; i++)
                #pragma unroll
                for (int j = 0; j < 4; j++)
                    acc[i][j] = fmaf(a[i], b[j], acc[i][j]);
        }
        __syncthreads();
    }

    const float4 bv = *(const float4*)(bias + bn + tx * 4);

    if (MODE == 2) {
        #pragma unroll
        for (int i = 0; i < 8; i++) {
            int m = bm + ty * 8 + i;
            float4 s = *(const float4*)(shortcut + (size_t)m * CDIM + bn + tx * 4);
            float4 o;
            o.x = acc[i][0] + bv.x + s.x;
            o.y = acc[i][1] + bv.y + s.y;
            o.z = acc[i][2] + bv.z + s.z;
            o.w = acc[i][3] + bv.w + s.w;
            *(float4*)(out + (size_t)m * CDIM + bn + tx * 4) = o;
        }
    } else {
        #pragma unroll
        for (int i = 0; i < 8; i++) {
            acc[i][0] += bv.x; acc[i][1] += bv.y;
            acc[i][2] += bv.z; acc[i][3] += bv.w;
            // row sum-of-squares over this 64-wide head chunk (16 tx lanes)
            float ssq = acc[i][0]*acc[i][0] + acc[i][1]*acc[i][1]
                      + acc[i][2]*acc[i][2] + acc[i][3]*acc[i][3];
            #pragma unroll
            for (int off = 1; off < 16; off <<= 1)
                ssq += __shfl_xor_sync(0xffffffffu, ssq, off);
            float rn = 1.0f / fmaxf(sqrtf(ssq), 1e-12f);
            float4 o = make_float4(acc[i][0]*rn, acc[i][1]*rn,
                                   acc[i][2]*rn, acc[i][3]*rn);
            int m = bm + ty * 8 + i;
            float* dst;
            if (MODE == 0) {
                int bt = m >> 8, lq = m & 255;
                int h = blockIdx.x;
                dst = g_qh + (((size_t)(bt * NH + h)) * LQ + lq) * HD + tx * 4;
            } else {
                int bt = m >> 9, lk = m & 511;
                int cb = blockIdx.x;           // 0..15, <8 -> K heads, >=8 -> V heads
                float* base = (cb < 8) ? g_kh : g_vh;
                int h = cb & 7;
                dst = base + (((size_t)(bt * NH + h)) * LK + lk) * HD + tx * 4;
            }
            *(float4*)dst = o;
        }
    }
}

// ---------------------------------------------------------------------------
// Attention: one block per (bt, h, 32-row q-tile). 256 threads = 8 warps.
// Warp w owns q-rows w*4..w*4+3; lane owns 2 k-cols (phase 1) / 2 d-cols (ph 2)
// ---------------------------------------------------------------------------
__global__ __launch_bounds__(256)
void attn_kernel()
{
    extern __shared__ float sm[];
    float* Qs  = sm;                       // [64][36]  Q transposed (d-major)
    float* KVs = sm + 64 * 36;             // [64][68]  K transposed / V row-major
    float* P   = sm + 64 * 36 + 64 * 68;   // [32][512] probs

    const int tid  = threadIdx.x;
    const int w    = tid >> 5;
    const int lane = tid & 31;
    const int qt   = blockIdx.x;   // 0..7
    const int h    = blockIdx.y;
    const int bt   = blockIdx.z;

    const float* Qg = g_qh + (((size_t)(bt * NH + h)) * LQ + qt * 32) * HD;
    const float* Kg = g_kh + ((size_t)(bt * NH + h)) * LK * HD;
    const float* Vg = g_vh + ((size_t)(bt * NH + h)) * LK * HD;

    // Load Q (32x64) transposed: Qs[d][r]
    #pragma unroll
    for (int l = 0; l < 2; l++) {
        int idx = tid + l * 256;
        int r = idx >> 4;
        int c = (idx & 15) * 4;
        float4 v = *(const float4*)(Qg + r * HD + c);
        Qs[(c + 0) * 36 + r] = v.x;
        Qs[(c + 1) * 36 + r] = v.y;
        Qs[(c + 2) * 36 + r] = v.z;
        Qs[(c + 3) * 36 + r] = v.w;
    }

    float s[4][16];
    #pragma unroll
    for (int i = 0; i < 4; i++)
        #pragma unroll
        for (int j = 0; j < 16; j++) s[i][j] = 0.f;

    // ---- Phase 1: S = Q K^T over 8 k-tiles of 64 ----
    for (int t = 0; t < 8; t++) {
        __syncthreads();
        #pragma unroll
        for (int l = 0; l < 4; l++) {
            int idx = tid + l * 256;
            int kk = idx >> 4;
            int c = (idx & 15) * 4;
            float4 v = *(const float4*)(Kg + (t * 64 + kk) * HD + c);
            KVs[(c + 0) * 68 + kk] = v.x;
            KVs[(c + 1) * 68 + kk] = v.y;
            KVs[(c + 2) * 68 + kk] = v.z;
            KVs[(c + 3) * 68 + kk] = v.w;
        }
        __syncthreads();
        #pragma unroll 4
        for (int d = 0; d < 64; d++) {
            float4 qv = *(const float4*)&Qs[d * 36 + w * 4];
            float2 kv = *(const float2*)&KVs[d * 68 + lane * 2];
            s[0][t*2+0] = fmaf(qv.x, kv.x, s[0][t*2+0]);
            s[0][t*2+1] = fmaf(qv.x, kv.y, s[0][t*2+1]);
            s[1][t*2+0] = fmaf(qv.y, kv.x, s[1][t*2+0]);
            s[1][t*2+1] = fmaf(qv.y, kv.y, s[1][t*2+1]);
            s[2][t*2+0] = fmaf(qv.z, kv.x, s[2][t*2+0]);
            s[2][t*2+1] = fmaf(qv.z, kv.y, s[2][t*2+1]);
            s[3][t*2+0] = fmaf(qv.w, kv.x, s[3][t*2+0]);
            s[3][t*2+1] = fmaf(qv.w, kv.y, s[3][t*2+1]);
        }
    }

    // ---- softmax (scale 1/8) + write P ----
    #pragma unroll
    for (int i = 0; i < 4; i++) {
        float mx = -1e30f;
        #pragma unroll
        for (int j = 0; j < 16; j++) mx = fmaxf(mx, s[i][j]);
        #pragma unroll
        for (int off = 16; off > 0; off >>= 1)
            mx = fmaxf(mx, __shfl_xor_sync(0xffffffffu, mx, off));
        float lsum = 0.f;
        #pragma unroll
        for (int j = 0; j < 16; j++) {
            s[i][j] = expf((s[i][j] - mx) * 0.125f);
            lsum += s[i][j];
        }
        #pragma unroll
        for (int off = 16; off > 0; off >>= 1)
            lsum += __shfl_xor_sync(0xffffffffu, lsum, off);
        float rl = 1.f / lsum;
        #pragma unroll
        for (int t = 0; t < 8; t++) {
            float2 pv = make_float2(s[i][t*2] * rl, s[i][t*2+1] * rl);
            *(float2*)&P[(w*4 + i) * 512 + t * 64 + lane * 2] = pv;
        }
    }

    // ---- Phase 2: O = P V ----
    float o[4][2];
    #pragma unroll
    for (int i = 0; i < 4; i++) { o[i][0] = 0.f; o[i][1] = 0.f; }

    for (int t = 0; t < 8; t++) {
        __syncthreads();
        #pragma unroll
        for (int l = 0; l < 4; l++) {
            int idx = tid + l * 256;
            int kk = idx >> 4;
            int c = (idx & 15) * 4;
            *(float4*)&KVs[kk * 68 + c] = *(const float4*)(Vg + (t * 64 + kk) * HD + c);
        }
        __syncthreads();
        #pragma unroll 4
        for (int kk = 0; kk < 64; kk++) {
            float2 vv = *(const float2*)&KVs[kk * 68 + lane * 2];
            int k = t * 64 + kk;
            float p0 = P[(w*4 + 0) * 512 + k];
            float p1 = P[(w*4 + 1) * 512 + k];
            float p2 = P[(w*4 + 2) * 512 + k];
            float p3 = P[(w*4 + 3) * 512 + k];
            o[0][0] = fmaf(p0, vv.x, o[0][0]); o[0][1] = fmaf(p0, vv.y, o[0][1]);
            o[1][0] = fmaf(p1, vv.x, o[1][0]); o[1][1] = fmaf(p1, vv.y, o[1][1]);
            o[2][0] = fmaf(p2, vv.x, o[2][0]); o[2][1] = fmaf(p2, vv.y, o[2][1]);
            o[3][0] = fmaf(p3, vv.x, o[3][0]); o[3][1] = fmaf(p3, vv.y, o[3][1]);
        }
    }

    // store merged-head layout: xm[bt][lq][h*64 + d]
    float* Og = g_xm + ((size_t)bt * LQ + qt * 32) * CDIM + h * 64;
    #pragma unroll
    for (int i = 0; i < 4; i++)
        *(float2*)(Og + (w*4 + i) * CDIM + lane * 2) = make_float2(o[i][0], o[i][1]);
}

// ---------------------------------------------------------------------------
extern "C" void kernel_launch(void* const* d_in, const int* in_sizes, int n_in,
                              void* d_out, int out_size)
{
    const float* q   = (const float*)d_in[0];
    const float* kv  = (const float*)d_in[1];
    const float* Wq  = (const float*)d_in[2];
    const float* bq  = (const float*)d_in[3];
    const float* Wkv = (const float*)d_in[4];
    const float* bkv = (const float*)d_in[5];
    const float* Wm  = (const float*)d_in[6];
    const float* bm  = (const float*)d_in[7];
    float* out = (float*)d_out;

    const int ATTN_SMEM = (64 * 36 + 64 * 68 + 32 * 512) * 4;  // 92160 B
    cudaFuncSetAttribute(attn_kernel,
                         cudaFuncAttributeMaxDynamicSharedMemorySize, ATTN_SMEM);

    // 1) Q projection + L2 normalize   (M=16384, N=512)
    gemm_kernel<0><<<dim3(8, 128), 256>>>(q, Wq, bq, nullptr, nullptr);
    // 2) KV projection + L2 normalize  (M=32768, N=1024)
    gemm_kernel<1><<<dim3(16, 256), 256>>>(kv, Wkv, bkv, nullptr, nullptr);
    // 3) cosine attention
    attn_kernel<<<dim3(8, 8, 64), 256, ATTN_SMEM>>>();
    // 4) output projection + bias + residual
    gemm_kernel<2><<<dim3(8, 128), 256>>>(nullptr, Wm, bm, q, out);
}

// round 2
// speedup vs baseline: 4.7943x; 4.7943x over previous
#include <cuda_runtime.h>
#include <cuda_bf16.h>
#include <math.h>

#define BT_N 64
#define LQ   256
#define LK   512
#define CDIM 512
#define NH   8
#define HD   64

typedef __nv_bfloat16 bf16;

// ---- device scratch (bf16 everywhere) ----
__device__ bf16 g_qbf [(size_t)16384 * 512];
__device__ bf16 g_kvbf[(size_t)32768 * 512];
__device__ bf16 g_wq  [512 * 512];
__device__ bf16 g_wkv [1024 * 512];
__device__ bf16 g_wm  [512 * 512];
__device__ bf16 g_qh  [(size_t)BT_N * NH * LQ * HD];
__device__ bf16 g_kh  [(size_t)BT_N * NH * LK * HD];
__device__ bf16 g_vt  [(size_t)BT_N * NH * HD * LK];   // V transposed: [bt][h][d][lk]
__device__ bf16 g_xm  [(size_t)BT_N * LQ * CDIM];

// pack two floats -> bf16x2 (lo at lower address)
__device__ __forceinline__ unsigned pk(float lo, float hi) {
    unsigned r;
    asm("cvt.rn.bf16x2.f32 %0, %1, %2;" : "=r"(r) : "f"(hi), "f"(lo));
    return r;
}

__device__ __forceinline__ void mma16816(float* d, const unsigned* a, const unsigned* b) {
    asm volatile(
        "mma.sync.aligned.m16n8k16.row.col.f32.bf16.bf16.f32 "
        "{%0,%1,%2,%3},{%4,%5,%6,%7},{%8,%9},{%0,%1,%2,%3};"
        : "+f"(d[0]), "+f"(d[1]), "+f"(d[2]), "+f"(d[3])
        : "r"(a[0]), "r"(a[1]), "r"(a[2]), "r"(a[3]), "r"(b[0]), "r"(b[1]));
}

// ---------------------------------------------------------------------------
// fp32 -> bf16 conversion (8 elems/thread)
// ---------------------------------------------------------------------------
template<int W>
__global__ void convert_kernel(const float* __restrict__ src, int n8) {
    int i = blockIdx.x * blockDim.x + threadIdx.x;
    if (i >= n8) return;
    const float4 a = ((const float4*)src)[2 * i];
    const float4 b = ((const float4*)src)[2 * i + 1];
    uint4 o = make_uint4(pk(a.x, a.y), pk(a.z, a.w), pk(b.x, b.y), pk(b.z, b.w));
    bf16* dst = (W == 0) ? g_qbf : (W == 1) ? g_kvbf :
                (W == 2) ? g_wq  : (W == 3) ? g_wkv  : g_wm;
    ((uint4*)dst)[i] = o;
}

// ---------------------------------------------------------------------------
// bf16 GEMM (NT): out[m][n] = sum_k A[m][k] * W[n][k] (+bias)
// BM=128, BN=128, BK=32, 256 threads, 8 warps (2M x 4N), warp tile 64x32.
// MODE 0: A=g_qbf,  W=g_wq;  epilogue L2-norm per 64-chunk -> g_qh (bf16)
// MODE 1: A=g_kvbf, W=g_wkv; epilogue L2-norm -> g_kh / g_vt (V transposed)
// MODE 2: A=g_xm,   W=g_wm;  epilogue +bias+shortcut -> out (fp32)
// ---------------------------------------------------------------------------
template<int MODE>
__global__ __launch_bounds__(256)
void gemm_bf16(const float* __restrict__ bias,
               const float* __restrict__ shortcut,
               float* __restrict__ out)
{
    __shared__ bf16 As[128 * 40];
    __shared__ bf16 Bs[128 * 40];
    __shared__ float sred[512];

    const int tid   = threadIdx.x;
    const int lane  = tid & 31;
    const int wid   = tid >> 5;
    const int warpM = wid >> 2;       // 0..1
    const int warpN = wid & 3;        // 0..3
    const int g     = lane >> 2;      // 0..7
    const int t2    = (lane & 3) * 2; // 0,2,4,6
    const int bm    = blockIdx.y * 128;
    const int bn    = blockIdx.x * 128;

    const bf16* A = (MODE == 0) ? g_qbf : (MODE == 1) ? g_kvbf : g_xm;
    const bf16* W = (MODE == 0) ? g_wq  : (MODE == 1) ? g_wkv  : g_wm;
    const bf16* Ab = A + (size_t)bm * CDIM;
    const bf16* Wb = W + (size_t)bn * CDIM;

    float acc[4][4][4] = {};

    for (int kt = 0; kt < CDIM; kt += 32) {
        #pragma unroll
        for (int it = 0; it < 2; it++) {
            int idx = tid + it * 256;
            int row = idx >> 2, c = (idx & 3) * 8;
            *(uint4*)&As[row * 40 + c] = *(const uint4*)&Ab[(size_t)row * CDIM + kt + c];
            *(uint4*)&Bs[row * 40 + c] = *(const uint4*)&Wb[(size_t)row * CDIM + kt + c];
        }
        __syncthreads();
        #pragma unroll
        for (int ks = 0; ks < 2; ks++) {
            const int ko = ks * 16;
            unsigned af[4][4], bfr[4][2];
            #pragma unroll
            for (int ma = 0; ma < 4; ma++) {
                int r = warpM * 64 + ma * 16 + g;
                af[ma][0] = *(const unsigned*)&As[r * 40 + ko + t2];
                af[ma][1] = *(const unsigned*)&As[(r + 8) * 40 + ko + t2];
                af[ma][2] = *(const unsigned*)&As[r * 40 + ko + t2 + 8];
                af[ma][3] = *(const unsigned*)&As[(r + 8) * 40 + ko + t2 + 8];
            }
            #pragma unroll
            for (int nb = 0; nb < 4; nb++) {
                int n = warpN * 32 + nb * 8 + g;
                bfr[nb][0] = *(const unsigned*)&Bs[n * 40 + ko + t2];
                bfr[nb][1] = *(const unsigned*)&Bs[n * 40 + ko + t2 + 8];
            }
            #pragma unroll
            for (int ma = 0; ma < 4; ma++)
                #pragma unroll
                for (int nb = 0; nb < 4; nb++)
                    mma16816(acc[ma][nb], af[ma], bfr[nb]);
        }
        __syncthreads();
    }

    // bias add
    float2 bv[4];
    #pragma unroll
    for (int nb = 0; nb < 4; nb++)
        bv[nb] = *(const float2*)&bias[bn + warpN * 32 + nb * 8 + t2];
    #pragma unroll
    for (int ma = 0; ma < 4; ma++)
        #pragma unroll
        for (int nb = 0; nb < 4; nb++) {
            acc[ma][nb][0] += bv[nb].x; acc[ma][nb][1] += bv[nb].y;
            acc[ma][nb][2] += bv[nb].x; acc[ma][nb][3] += bv[nb].y;
        }

    if (MODE == 2) {
        #pragma unroll
        for (int ma = 0; ma < 4; ma++)
            #pragma unroll
            for (int h2 = 0; h2 < 2; h2++) {
                int m = bm + warpM * 64 + ma * 16 + h2 * 8 + g;
                #pragma unroll
                for (int nb = 0; nb < 4; nb++) {
                    int n = bn + warpN * 32 + nb * 8 + t2;
                    float2 s = *(const float2*)&shortcut[(size_t)m * CDIM + n];
                    float2 o;
                    o.x = acc[ma][nb][h2 * 2 + 0] + s.x;
                    o.y = acc[ma][nb][h2 * 2 + 1] + s.y;
                    *(float2*)&out[(size_t)m * CDIM + n] = o;
                }
            }
    } else {
        // row-wise sum of squares over each 64-wide head chunk
        float ssq[4][2];
        #pragma unroll
        for (int ma = 0; ma < 4; ma++)
            #pragma unroll
            for (int h2 = 0; h2 < 2; h2++) {
                float s = 0.f;
                #pragma unroll
                for (int nb = 0; nb < 4; nb++) {
                    float x = acc[ma][nb][h2 * 2], y = acc[ma][nb][h2 * 2 + 1];
                    s += x * x + y * y;
                }
                s += __shfl_xor_sync(0xffffffffu, s, 1);
                s += __shfl_xor_sync(0xffffffffu, s, 2);
                ssq[ma][h2] = s;
            }
        if ((lane & 3) == 0) {
            #pragma unroll
            for (int ma = 0; ma < 4; ma++)
                #pragma unroll
                for (int h2 = 0; h2 < 2; h2++)
                    sred[wid * 64 + ma * 16 + h2 * 8 + g] = ssq[ma][h2];
        }
        __syncthreads();
        #pragma unroll
        for (int ma = 0; ma < 4; ma++)
            #pragma unroll
            for (int h2 = 0; h2 < 2; h2++) {
                int r = ma * 16 + h2 * 8 + g;
                float tot = sred[(wid & ~1) * 64 + r] + sred[((wid & ~1) + 1) * 64 + r];
                float rn = 1.f / fmaxf(sqrtf(tot), 1e-12f);
                int m = bm + warpM * 64 + r;
                #pragma unroll
                for (int nb = 0; nb < 4; nb++) {
                    int n = bn + warpN * 32 + nb * 8 + t2;
                    float v0 = acc[ma][nb][h2 * 2] * rn;
                    float v1 = acc[ma][nb][h2 * 2 + 1] * rn;
                    if (MODE == 0) {
                        int bt = m >> 8, lq = m & 255;
                        int h = n >> 6, d = n & 63;
                        *(unsigned*)&g_qh[(((size_t)(bt * 8 + h)) * 256 + lq) * 64 + d] = pk(v0, v1);
                    } else {
                        int bt = m >> 9, lk = m & 511;
                        if (n < 512) {
                            int h = n >> 6, d = n & 63;
                            *(unsigned*)&g_kh[(((size_t)(bt * 8 + h)) * 512 + lk) * 64 + d] = pk(v0, v1);
                        } else {
                            int h = (n >> 6) - 8, d = n & 63;
                            size_t base = (((size_t)(bt * 8 + h)) * 64);
                            g_vt[(base + d)     * 512 + lk] = __float2bfloat16(v0);
                            g_vt[(base + d + 1) * 512 + lk] = __float2bfloat16(v1);
                        }
                    }
                }
            }
    }
}

// ---------------------------------------------------------------------------
// Attention: block = (q-tile of 128, h, bt). 256 threads, 8 warps x 16 q-rows.
// Scores bounded (|dot|<=1) -> no max subtraction, no online rescale.
// ---------------------------------------------------------------------------
__global__ __launch_bounds__(256)
void attn_bf16()
{
    __shared__ bf16 Qs[128 * 72];
    __shared__ bf16 Ks[64 * 72];
    __shared__ bf16 Vs[64 * 72];   // [d][key]

    const int tid  = threadIdx.x;
    const int lane = tid & 31;
    const int wid  = tid >> 5;
    const int g    = lane >> 2;
    const int t2   = (lane & 3) * 2;
    const int qt   = blockIdx.x;
    const int h    = blockIdx.y;
    const int bt   = blockIdx.z;

    const bf16* Qg = g_qh + (((size_t)(bt * 8 + h)) * 256 + qt * 128) * 64;
    const bf16* Kg = g_kh + ((size_t)(bt * 8 + h)) * 512 * 64;
    const bf16* Vg = g_vt + ((size_t)(bt * 8 + h)) * 64 * 512;

    // Q tile 128x64 -> smem
    #pragma unroll
    for (int it = 0; it < 4; it++) {
        int idx = tid + it * 256;
        int row = idx >> 3, c = (idx & 7) * 8;
        *(uint4*)&Qs[row * 72 + c] = *(const uint4*)&Qg[(size_t)row * 64 + c];
    }
    __syncthreads();

    // preload Q fragments (per-warp, reused for all k-tiles)
    unsigned qf[4][4];
    {
        int r = wid * 16 + g;
        #pragma unroll
        for (int ka = 0; ka < 4; ka++) {
            qf[ka][0] = *(const unsigned*)&Qs[r * 72 + ka * 16 + t2];
            qf[ka][1] = *(const unsigned*)&Qs[(r + 8) * 72 + ka * 16 + t2];
            qf[ka][2] = *(const unsigned*)&Qs[r * 72 + ka * 16 + t2 + 8];
            qf[ka][3] = *(const unsigned*)&Qs[(r + 8) * 72 + ka * 16 + t2 + 8];
        }
    }

    float oacc[8][4] = {};
    float lsum0 = 0.f, lsum1 = 0.f;
    const float sc = 0.125f * 1.4426950408889634f;   // log2(e)/sqrt(64)

    for (int t = 0; t < 8; t++) {
        __syncthreads();
        #pragma unroll
        for (int it = 0; it < 2; it++) {
            int idx = tid + it * 256;
            int row = idx >> 3, c = (idx & 7) * 8;
            *(uint4*)&Ks[row * 72 + c] = *(const uint4*)&Kg[(size_t)(t * 64 + row) * 64 + c];
            *(uint4*)&Vs[row * 72 + c] = *(const uint4*)&Vg[(size_t)row * 512 + t * 64 + c];
        }
        __syncthreads();

        // S = Q K^T  (warp: 16 x 64)
        float sacc[8][4] = {};
        #pragma unroll
        for (int ka = 0; ka < 4; ka++) {
            #pragma unroll
            for (int nb = 0; nb < 8; nb++) {
                unsigned bfr[2];
                int n = nb * 8 + g;
                bfr[0] = *(const unsigned*)&Ks[n * 72 + ka * 16 + t2];
                bfr[1] = *(const unsigned*)&Ks[n * 72 + ka * 16 + t2 + 8];
                mma16816(sacc[nb], qf[ka], bfr);
            }
        }

        // exp (bounded arg), accumulate row sums
        #pragma unroll
        for (int nb = 0; nb < 8; nb++) {
            #pragma unroll
            for (int i = 0; i < 4; i++) {
                float e;
                asm("ex2.approx.f32 %0, %1;" : "=f"(e) : "f"(sacc[nb][i] * sc));
                sacc[nb][i] = e;
            }
            lsum0 += sacc[nb][0] + sacc[nb][1];
            lsum1 += sacc[nb][2] + sacc[nb][3];
        }

        // O += P V  (P fragments come straight from sacc layout)
        #pragma unroll
        for (int kk = 0; kk < 4; kk++) {
            unsigned pf[4];
            pf[0] = pk(sacc[2 * kk][0],     sacc[2 * kk][1]);
            pf[1] = pk(sacc[2 * kk][2],     sacc[2 * kk][3]);
            pf[2] = pk(sacc[2 * kk + 1][0], sacc[2 * kk + 1][1]);
            pf[3] = pk(sacc[2 * kk + 1][2], sacc[2 * kk + 1][3]);
            #pragma unroll
            for (int nb = 0; nb < 8; nb++) {
                unsigned vf[2];
                int n = nb * 8 + g;
                vf[0] = *(const unsigned*)&Vs[n * 72 + kk * 16 + t2];
                vf[1] = *(const unsigned*)&Vs[n * 72 + kk * 16 + t2 + 8];
                mma16816(oacc[nb], pf, vf);
            }
        }
    }

    lsum0 += __shfl_xor_sync(0xffffffffu, lsum0, 1);
    lsum0 += __shfl_xor_sync(0xffffffffu, lsum0, 2);
    lsum1 += __shfl_xor_sync(0xffffffffu, lsum1, 1);
    lsum1 += __shfl_xor_sync(0xffffffffu, lsum1, 2);
    const float rl0 = 1.f / lsum0, rl1 = 1.f / lsum1;

    bf16* Og = g_xm + ((size_t)bt * 256 + qt * 128) * 512 + h * 64;
    const int r0 = wid * 16 + g;
    #pragma unroll
    for (int nb = 0; nb < 8; nb++) {
        int n = nb * 8 + t2;
        *(unsigned*)&Og[(size_t)r0 * 512 + n]       = pk(oacc[nb][0] * rl0, oacc[nb][1] * rl0);
        *(unsigned*)&Og[(size_t)(r0 + 8) * 512 + n] = pk(oacc[nb][2] * rl1, oacc[nb][3] * rl1);
    }
}

// ---------------------------------------------------------------------------
extern "C" void kernel_launch(void* const* d_in, const int* in_sizes, int n_in,
                              void* d_out, int out_size)
{
    const float* q   = (const float*)d_in[0];
    const float* kv  = (const float*)d_in[1];
    const float* Wq  = (const float*)d_in[2];
    const float* bq  = (const float*)d_in[3];
    const float* Wkv = (const float*)d_in[4];
    const float* bkv = (const float*)d_in[5];
    const float* Wm  = (const float*)d_in[6];
    const float* bm  = (const float*)d_in[7];
    float* out = (float*)d_out;

    // bf16 conversions
    convert_kernel<0><<<(16384 * 512 / 8) / 256, 256>>>(q,   16384 * 512 / 8);
    convert_kernel<1><<<(32768 * 512 / 8) / 256, 256>>>(kv,  32768 * 512 / 8);
    convert_kernel<2><<<(512 * 512 / 8)   / 256, 256>>>(Wq,  512 * 512 / 8);
    convert_kernel<3><<<(1024 * 512 / 8)  / 256, 256>>>(Wkv, 1024 * 512 / 8);
    convert_kernel<4><<<(512 * 512 / 8)   / 256, 256>>>(Wm,  512 * 512 / 8);

    // 1) Q projection + normalize
    gemm_bf16<0><<<dim3(4, 128), 256>>>(bq, nullptr, nullptr);
    // 2) KV projection + normalize (V stored transposed)
    gemm_bf16<1><<<dim3(8, 256), 256>>>(bkv, nullptr, nullptr);
    // 3) cosine attention
    attn_bf16<<<dim3(2, 8, 64), 256>>>();
    // 4) output projection + bias + residual
    gemm_bf16<2><<<dim3(4, 128), 256>>>(bm, q, out);
}

// round 4
// speedup vs baseline: 5.4997x; 1.1471x over previous
#include <cuda_runtime.h>
#include <cuda_bf16.h>
#include <math.h>
#include <stdint.h>

#define BT_N 64
#define LQ   256
#define LK   512
#define CDIM 512
#define NH   8
#define HD   64

typedef __nv_bfloat16 bf16;

// ---- device scratch ----
__device__ bf16 g_qbf [(size_t)16384 * 512];
__device__ bf16 g_kvbf[(size_t)32768 * 512];
__device__ bf16 g_wq  [512 * 512];
__device__ bf16 g_wkv [1024 * 512];
__device__ bf16 g_wm  [512 * 512];
__device__ bf16 g_qh  [(size_t)BT_N * NH * LQ * HD];
__device__ bf16 g_kh  [(size_t)BT_N * NH * LK * HD];
__device__ bf16 g_vt  [(size_t)BT_N * NH * HD * LK];   // V transposed: [bt][h][d][lk]
__device__ bf16 g_xm  [(size_t)BT_N * LQ * CDIM];

// ---------------------------------------------------------------------------
__device__ __forceinline__ unsigned pk(float lo, float hi) {
    unsigned r;
    asm("cvt.rn.bf16x2.f32 %0, %1, %2;" : "=r"(r) : "f"(hi), "f"(lo));
    return r;
}
__device__ __forceinline__ uint32_t smem_u32(const void* p) {
    uint32_t a;
    asm("{ .reg .u64 t; cvta.to.shared.u64 t, %1; cvt.u32.u64 %0, t; }" : "=r"(a) : "l"(p));
    return a;
}
__device__ __forceinline__ void cp_async16(uint32_t dst, const void* src) {
    asm volatile("cp.async.cg.shared.global [%0], [%1], 16;" :: "r"(dst), "l"(src));
}
__device__ __forceinline__ void cp_commit() { asm volatile("cp.async.commit_group;" ::: "memory"); }
template<int N> __device__ __forceinline__ void cp_wait() { asm volatile("cp.async.wait_group %0;" :: "n"(N) : "memory"); }

__device__ __forceinline__ void mma16816(float* d, const unsigned* a, const unsigned* b) {
    asm volatile(
        "mma.sync.aligned.m16n8k16.row.col.f32.bf16.bf16.f32 "
        "{%0,%1,%2,%3},{%4,%5,%6,%7},{%8,%9},{%0,%1,%2,%3};"
        : "+f"(d[0]), "+f"(d[1]), "+f"(d[2]), "+f"(d[3])
        : "r"(a[0]), "r"(a[1]), "r"(a[2]), "r"(a[3]), "r"(b[0]), "r"(b[1]));
}

// ---------------------------------------------------------------------------
// fp32 -> bf16 conversion (8 elems/thread)
// ---------------------------------------------------------------------------
template<int W>
__global__ void convert_kernel(const float* __restrict__ src, int n8) {
    int i = blockIdx.x * blockDim.x + threadIdx.x;
    if (i >= n8) return;
    const float4 a = ((const float4*)src)[2 * i];
    const float4 b = ((const float4*)src)[2 * i + 1];
    uint4 o = make_uint4(pk(a.x, a.y), pk(a.z, a.w), pk(b.x, b.y), pk(b.z, b.w));
    bf16* dst = (W == 0) ? g_qbf : (W == 1) ? g_kvbf :
                (W == 2) ? g_wq  : (W == 3) ? g_wkv  : g_wm;
    ((uint4*)dst)[i] = o;
}

// ---------------------------------------------------------------------------
// bf16 GEMM (NT), 3-stage cp.async pipeline.
// BM=128, BN=128, BK=32, 256 threads (8 warps: 2M x 4N), warp tile 64x32.
// smem: A stages [0, 3*10240)B, B stages [30720, 61440)B; row stride 40 bf16.
// ---------------------------------------------------------------------------
#define GSMEM 61440

template<int MODE>
__global__ __launch_bounds__(256)
void gemm_bf16(const float* __restrict__ bias,
               const float* __restrict__ shortcut,
               float* __restrict__ out)
{
    extern __shared__ bf16 dsm[];
    __shared__ float sred[512];
    const uint32_t smA = smem_u32(dsm);
    const uint32_t smB = smA + 30720;

    const int tid   = threadIdx.x;
    const int lane  = tid & 31;
    const int wid   = tid >> 5;
    const int warpM = wid >> 2;
    const int warpN = wid & 3;
    const int g     = lane >> 2;
    const int t2    = (lane & 3) * 2;
    const int bm    = blockIdx.y * 128;
    const int bn    = blockIdx.x * 128;

    const bf16* A = (MODE == 0) ? g_qbf : (MODE == 1) ? g_kvbf : g_xm;
    const bf16* W = (MODE == 0) ? g_wq  : (MODE == 1) ? g_wkv  : g_wm;
    const bf16* Ab = A + (size_t)bm * CDIM;
    const bf16* Wb = W + (size_t)bn * CDIM;

    // per-thread load coords (2 chunks each for A and B per tile)
    const int c0row = tid >> 1;            // unused split; use generic below
    (void)c0row;

    auto load_tile = [&](int t) {
        const int kt = t * 32;
        const int stage = t % 3;
        const uint32_t ab = smA + stage * 10240;
        const uint32_t bb = smB + stage * 10240;
        #pragma unroll
        for (int it = 0; it < 2; it++) {
            int c   = tid + it * 256;      // 0..511
            int row = c >> 2;
            int cc  = c & 3;               // 16B chunk in row
            cp_async16(ab + row * 80 + cc * 16, Ab + (size_t)row * CDIM + kt + cc * 8);
            cp_async16(bb + row * 80 + cc * 16, Wb + (size_t)row * CDIM + kt + cc * 8);
        }
    };

    float acc[4][4][4] = {};

    load_tile(0); cp_commit();
    load_tile(1); cp_commit();

    for (int t = 0; t < 16; t++) {
        cp_wait<1>();
        __syncthreads();
        if (t + 2 < 16) load_tile(t + 2);
        cp_commit();

        const bf16* Asp = dsm + (t % 3) * 5120;
        const bf16* Bsp = dsm + 15360 + (t % 3) * 5120;
        #pragma unroll
        for (int ks = 0; ks < 2; ks++) {
            const int ko = ks * 16;
            unsigned af[4][4], bfr[4][2];
            #pragma unroll
            for (int ma = 0; ma < 4; ma++) {
                int r = warpM * 64 + ma * 16 + g;
                af[ma][0] = *(const unsigned*)&Asp[r * 40 + ko + t2];
                af[ma][1] = *(const unsigned*)&Asp[(r + 8) * 40 + ko + t2];
                af[ma][2] = *(const unsigned*)&Asp[r * 40 + ko + t2 + 8];
                af[ma][3] = *(const unsigned*)&Asp[(r + 8) * 40 + ko + t2 + 8];
            }
            #pragma unroll
            for (int nb = 0; nb < 4; nb++) {
                int n = warpN * 32 + nb * 8 + g;
                bfr[nb][0] = *(const unsigned*)&Bsp[n * 40 + ko + t2];
                bfr[nb][1] = *(const unsigned*)&Bsp[n * 40 + ko + t2 + 8];
            }
            #pragma unroll
            for (int ma = 0; ma < 4; ma++)
                #pragma unroll
                for (int nb = 0; nb < 4; nb++)
                    mma16816(acc[ma][nb], af[ma], bfr[nb]);
        }
    }

    // bias add
    float2 bv[4];
    #pragma unroll
    for (int nb = 0; nb < 4; nb++)
        bv[nb] = *(const float2*)&bias[bn + warpN * 32 + nb * 8 + t2];
    #pragma unroll
    for (int ma = 0; ma < 4; ma++)
        #pragma unroll
        for (int nb = 0; nb < 4; nb++) {
            acc[ma][nb][0] += bv[nb].x; acc[ma][nb][1] += bv[nb].y;
            acc[ma][nb][2] += bv[nb].x; acc[ma][nb][3] += bv[nb].y;
        }

    if (MODE == 2) {
        #pragma unroll
        for (int ma = 0; ma < 4; ma++)
            #pragma unroll
            for (int h2 = 0; h2 < 2; h2++) {
                int m = bm + warpM * 64 + ma * 16 + h2 * 8 + g;
                #pragma unroll
                for (int nb = 0; nb < 4; nb++) {
                    int n = bn + warpN * 32 + nb * 8 + t2;
                    float2 s = *(const float2*)&shortcut[(size_t)m * CDIM + n];
                    float2 o;
                    o.x = acc[ma][nb][h2 * 2 + 0] + s.x;
                    o.y = acc[ma][nb][h2 * 2 + 1] + s.y;
                    *(float2*)&out[(size_t)m * CDIM + n] = o;
                }
            }
    } else {
        float ssq[4][2];
        #pragma unroll
        for (int ma = 0; ma < 4; ma++)
            #pragma unroll
            for (int h2 = 0; h2 < 2; h2++) {
                float s = 0.f;
                #pragma unroll
                for (int nb = 0; nb < 4; nb++) {
                    float x = acc[ma][nb][h2 * 2], y = acc[ma][nb][h2 * 2 + 1];
                    s += x * x + y * y;
                }
                s += __shfl_xor_sync(0xffffffffu, s, 1);
                s += __shfl_xor_sync(0xffffffffu, s, 2);
                ssq[ma][h2] = s;
            }
        __syncthreads();
        if ((lane & 3) == 0) {
            #pragma unroll
            for (int ma = 0; ma < 4; ma++)
                #pragma unroll
                for (int h2 = 0; h2 < 2; h2++)
                    sred[wid * 64 + ma * 16 + h2 * 8 + g] = ssq[ma][h2];
        }
        __syncthreads();
        #pragma unroll
        for (int ma = 0; ma < 4; ma++)
            #pragma unroll
            for (int h2 = 0; h2 < 2; h2++) {
                int r = ma * 16 + h2 * 8 + g;
                float tot = sred[(wid & ~1) * 64 + r] + sred[((wid & ~1) + 1) * 64 + r];
                float rn = 1.f / fmaxf(sqrtf(tot), 1e-12f);
                int m = bm + warpM * 64 + r;
                #pragma unroll
                for (int nb = 0; nb < 4; nb++) {
                    int n = bn + warpN * 32 + nb * 8 + t2;
                    float v0 = acc[ma][nb][h2 * 2] * rn;
                    float v1 = acc[ma][nb][h2 * 2 + 1] * rn;
                    if (MODE == 0) {
                        int bt = m >> 8, lq = m & 255;
                        int h = n >> 6, d = n & 63;
                        *(unsigned*)&g_qh[(((size_t)(bt * 8 + h)) * 256 + lq) * 64 + d] = pk(v0, v1);
                    } else {
                        int bt = m >> 9, lk = m & 511;
                        if (n < 512) {
                            int h = n >> 6, d = n & 63;
                            *(unsigned*)&g_kh[(((size_t)(bt * 8 + h)) * 512 + lk) * 64 + d] = pk(v0, v1);
                        } else {
                            int h = (n >> 6) - 8, d = n & 63;
                            size_t base = (((size_t)(bt * 8 + h)) * 64);
                            g_vt[(base + d)     * 512 + lk] = __float2bfloat16(v0);
                            g_vt[(base + d + 1) * 512 + lk] = __float2bfloat16(v1);
                        }
                    }
                }
            }
    }
}

// ---------------------------------------------------------------------------
// Attention, 3-stage cp.async on K/V. block = (128 q-rows, h, bt), 8 warps.
// dyn smem: Qs[128*72] | Ks[3][64*72] | Vs[3][64*72]  = 73728 B
// ---------------------------------------------------------------------------
#define ASMEM 73728

__global__ __launch_bounds__(256)
void attn_bf16()
{
    extern __shared__ bf16 dsm[];
    bf16* Qs = dsm;                       // 9216 elems
    const uint32_t smK = smem_u32(dsm) + 9216 * 2;
    const uint32_t smV = smK + 13824 * 2;

    const int tid  = threadIdx.x;
    const int lane = tid & 31;
    const int wid  = tid >> 5;
    const int g    = lane >> 2;
    const int t2   = (lane & 3) * 2;
    const int qt   = blockIdx.x;
    const int h    = blockIdx.y;
    const int bt   = blockIdx.z;

    const bf16* Qg = g_qh + (((size_t)(bt * 8 + h)) * 256 + qt * 128) * 64;
    const bf16* Kg = g_kh + ((size_t)(bt * 8 + h)) * 512 * 64;
    const bf16* Vg = g_vt + ((size_t)(bt * 8 + h)) * 64 * 512;

    auto load_kv = [&](int t) {
        const int stage = t % 3;
        const uint32_t kb = smK + stage * 4608 * 2;
        const uint32_t vb = smV + stage * 4608 * 2;
        #pragma unroll
        for (int it = 0; it < 2; it++) {
            int c   = tid + it * 256;     // 0..511
            int row = c >> 3;
            int cc  = c & 7;              // 16B chunk
            cp_async16(kb + row * 144 + cc * 16, Kg + (size_t)(t * 64 + row) * 64 + cc * 8);
            cp_async16(vb + row * 144 + cc * 16, Vg + (size_t)row * 512 + t * 64 + cc * 8);
        }
    };

    load_kv(0); cp_commit();
    load_kv(1); cp_commit();

    // Q tile 128x64 -> smem (plain)
    #pragma unroll
    for (int it = 0; it < 4; it++) {
        int idx = tid + it * 256;
        int row = idx >> 3, c = (idx & 7) * 8;
        *(uint4*)&Qs[row * 72 + c] = *(const uint4*)&Qg[(size_t)row * 64 + c];
    }
    __syncthreads();

    unsigned qf[4][4];
    {
        int r = wid * 16 + g;
        #pragma unroll
        for (int ka = 0; ka < 4; ka++) {
            qf[ka][0] = *(const unsigned*)&Qs[r * 72 + ka * 16 + t2];
            qf[ka][1] = *(const unsigned*)&Qs[(r + 8) * 72 + ka * 16 + t2];
            qf[ka][2] = *(const unsigned*)&Qs[r * 72 + ka * 16 + t2 + 8];
            qf[ka][3] = *(const unsigned*)&Qs[(r + 8) * 72 + ka * 16 + t2 + 8];
        }
    }

    float oacc[8][4] = {};
    float lsum0 = 0.f, lsum1 = 0.f;
    const float sc = 0.125f * 1.4426950408889634f;

    for (int t = 0; t < 8; t++) {
        cp_wait<1>();
        __syncthreads();
        if (t + 2 < 8) load_kv(t + 2);
        cp_commit();

        const bf16* Ksp = dsm + 9216 + (t % 3) * 4608;
        const bf16* Vsp = dsm + 9216 + 13824 + (t % 3) * 4608;

        float sacc[8][4] = {};
        #pragma unroll
        for (int ka = 0; ka < 4; ka++) {
            #pragma unroll
            for (int nb = 0; nb < 8; nb++) {
                unsigned bfr[2];
                int n = nb * 8 + g;
                bfr[0] = *(const unsigned*)&Ksp[n * 72 + ka * 16 + t2];
                bfr[1] = *(const unsigned*)&Ksp[n * 72 + ka * 16 + t2 + 8];
                mma16816(sacc[nb], qf[ka], bfr);
            }
        }

        #pragma unroll
        for (int nb = 0; nb < 8; nb++) {
            #pragma unroll
            for (int i = 0; i < 4; i++) {
                float e;
                asm("ex2.approx.f32 %0, %1;" : "=f"(e) : "f"(sacc[nb][i] * sc));
                sacc[nb][i] = e;
            }
            lsum0 += sacc[nb][0] + sacc[nb][1];
            lsum1 += sacc[nb][2] + sacc[nb][3];
        }

        #pragma unroll
        for (int kk = 0; kk < 4; kk++) {
            unsigned pf[4];
            pf[0] = pk(sacc[2 * kk][0],     sacc[2 * kk][1]);
            pf[1] = pk(sacc[2 * kk][2],     sacc[2 * kk][3]);
            pf[2] = pk(sacc[2 * kk + 1][0], sacc[2 * kk + 1][1]);
            pf[3] = pk(sacc[2 * kk + 1][2], sacc[2 * kk + 1][3]);
            #pragma unroll
            for (int nb = 0; nb < 8; nb++) {
                unsigned vf[2];
                int n = nb * 8 + g;
                vf[0] = *(const unsigned*)&Vsp[n * 72 + kk * 16 + t2];
                vf[1] = *(const unsigned*)&Vsp[n * 72 + kk * 16 + t2 + 8];
                mma16816(oacc[nb], pf, vf);
            }
        }
    }

    lsum0 += __shfl_xor_sync(0xffffffffu, lsum0, 1);
    lsum0 += __shfl_xor_sync(0xffffffffu, lsum0, 2);
    lsum1 += __shfl_xor_sync(0xffffffffu, lsum1, 1);
    lsum1 += __shfl_xor_sync(0xffffffffu, lsum1, 2);
    const float rl0 = 1.f / lsum0, rl1 = 1.f / lsum1;

    bf16* Og = g_xm + ((size_t)bt * 256 + qt * 128) * 512 + h * 64;
    const int r0 = wid * 16 + g;
    #pragma unroll
    for (int nb = 0; nb < 8; nb++) {
        int n = nb * 8 + t2;
        *(unsigned*)&Og[(size_t)r0 * 512 + n]       = pk(oacc[nb][0] * rl0, oacc[nb][1] * rl0);
        *(unsigned*)&Og[(size_t)(r0 + 8) * 512 + n] = pk(oacc[nb][2] * rl1, oacc[nb][3] * rl1);
    }
}

// ---------------------------------------------------------------------------
extern "C" void kernel_launch(void* const* d_in, const int* in_sizes, int n_in,
                              void* d_out, int out_size)
{
    const float* q   = (const float*)d_in[0];
    const float* kv  = (const float*)d_in[1];
    const float* Wq  = (const float*)d_in[2];
    const float* bq  = (const float*)d_in[3];
    const float* Wkv = (const float*)d_in[4];
    const float* bkv = (const float*)d_in[5];
    const float* Wm  = (const float*)d_in[6];
    const float* bm  = (const float*)d_in[7];
    float* out = (float*)d_out;

    cudaFuncSetAttribute(gemm_bf16<0>, cudaFuncAttributeMaxDynamicSharedMemorySize, GSMEM);
    cudaFuncSetAttribute(gemm_bf16<1>, cudaFuncAttributeMaxDynamicSharedMemorySize, GSMEM);
    cudaFuncSetAttribute(gemm_bf16<2>, cudaFuncAttributeMaxDynamicSharedMemorySize, GSMEM);
    cudaFuncSetAttribute(attn_bf16,    cudaFuncAttributeMaxDynamicSharedMemorySize, ASMEM);

    convert_kernel<0><<<(16384 * 512 / 8) / 256, 256>>>(q,   16384 * 512 / 8);
    convert_kernel<1><<<(32768 * 512 / 8) / 256, 256>>>(kv,  32768 * 512 / 8);
    convert_kernel<2><<<(512 * 512 / 8)   / 256, 256>>>(Wq,  512 * 512 / 8);
    convert_kernel<3><<<(1024 * 512 / 8)  / 256, 256>>>(Wkv, 1024 * 512 / 8);
    convert_kernel<4><<<(512 * 512 / 8)   / 256, 256>>>(Wm,  512 * 512 / 8);

    gemm_bf16<0><<<dim3(4, 128), 256, GSMEM>>>(bq, nullptr, nullptr);
    gemm_bf16<1><<<dim3(8, 256), 256, GSMEM>>>(bkv, nullptr, nullptr);
    attn_bf16<<<dim3(2, 8, 64), 256, ASMEM>>>();
    gemm_bf16<2><<<dim3(4, 128), 256, GSMEM>>>(bm, q, out);
}

// round 5
// speedup vs baseline: 5.8663x; 1.0667x over previous
#include <cuda_runtime.h>
#include <cuda_bf16.h>
#include <math.h>
#include <stdint.h>

#define BT_N 64
#define LQ   256
#define LK   512
#define CDIM 512
#define NH   8
#define HD   64

typedef __nv_bfloat16 bf16;

// ---- device scratch ----
__device__ bf16 g_qbf [(size_t)16384 * 512];
__device__ bf16 g_kvbf[(size_t)32768 * 512];
__device__ bf16 g_wq  [512 * 512];
__device__ bf16 g_wkv [1024 * 512];
__device__ bf16 g_wm  [512 * 512];
__device__ bf16 g_qh  [(size_t)BT_N * NH * LQ * HD];
__device__ bf16 g_kh  [(size_t)BT_N * NH * LK * HD];
__device__ bf16 g_vt  [(size_t)BT_N * NH * HD * LK];   // V transposed: [bt][h][d][lk]
__device__ bf16 g_xm  [(size_t)BT_N * LQ * CDIM];

// ---------------------------------------------------------------------------
__device__ __forceinline__ unsigned pk(float lo, float hi) {
    unsigned r;
    asm("cvt.rn.bf16x2.f32 %0, %1, %2;" : "=r"(r) : "f"(hi), "f"(lo));
    return r;
}
__device__ __forceinline__ uint32_t smem_u32(const void* p) {
    uint32_t a;
    asm("{ .reg .u64 t; cvta.to.shared.u64 t, %1; cvt.u32.u64 %0, t; }" : "=r"(a) : "l"(p));
    return a;
}
__device__ __forceinline__ void cp_async16(uint32_t dst, const void* src) {
    asm volatile("cp.async.cg.shared.global [%0], [%1], 16;" :: "r"(dst), "l"(src));
}
__device__ __forceinline__ void cp_commit() { asm volatile("cp.async.commit_group;" ::: "memory"); }
template<int N> __device__ __forceinline__ void cp_wait() { asm volatile("cp.async.wait_group %0;" :: "n"(N) : "memory"); }

__device__ __forceinline__ void ldm_x4(unsigned* r, uint32_t addr) {
    asm volatile("ldmatrix.sync.aligned.m8n8.x4.shared.b16 {%0,%1,%2,%3}, [%4];"
                 : "=r"(r[0]), "=r"(r[1]), "=r"(r[2]), "=r"(r[3]) : "r"(addr));
}

__device__ __forceinline__ void mma16816(float* d, const unsigned* a, unsigned b0, unsigned b1) {
    asm volatile(
        "mma.sync.aligned.m16n8k16.row.col.f32.bf16.bf16.f32 "
        "{%0,%1,%2,%3},{%4,%5,%6,%7},{%8,%9},{%0,%1,%2,%3};"
        : "+f"(d[0]), "+f"(d[1]), "+f"(d[2]), "+f"(d[3])
        : "r"(a[0]), "r"(a[1]), "r"(a[2]), "r"(a[3]), "r"(b0), "r"(b1));
}

// ---------------------------------------------------------------------------
// fp32 -> bf16 conversions (merged): inputs (q, kv) and weights (wq, wkv, wm)
// unit = 8 elements
// ---------------------------------------------------------------------------
#define Q8   (16384 * 512 / 8)
#define KV8  (32768 * 512 / 8)
#define WQ8  (512 * 512 / 8)
#define WKV8 (1024 * 512 / 8)
#define WM8  (512 * 512 / 8)

__device__ __forceinline__ void conv8(const float* src, bf16* dst, int i) {
    const float4 a = ((const float4*)src)[2 * i];
    const float4 b = ((const float4*)src)[2 * i + 1];
    ((uint4*)dst)[i] = make_uint4(pk(a.x, a.y), pk(a.z, a.w), pk(b.x, b.y), pk(b.z, b.w));
}

__global__ __launch_bounds__(256) void convert_inputs(const float* __restrict__ q,
                                                      const float* __restrict__ kv) {
    int i = blockIdx.x * blockDim.x + threadIdx.x;
    if (i < Q8) conv8(q, g_qbf, i);
    else        conv8(kv, g_kvbf, i - Q8);
}
__global__ __launch_bounds__(256) void convert_weights(const float* __restrict__ wq,
                                                       const float* __restrict__ wkv,
                                                       const float* __restrict__ wm) {
    int i = blockIdx.x * blockDim.x + threadIdx.x;
    if (i < WQ8)             conv8(wq, g_wq, i);
    else if (i < WQ8 + WKV8) conv8(wkv, g_wkv, i - WQ8);
    else                     conv8(wm, g_wm, i - WQ8 - WKV8);
}

// ---------------------------------------------------------------------------
// bf16 GEMM (NT), 3-stage cp.async pipeline + ldmatrix fragments.
// BM=128, BN=128, BK=32, 256 threads (8 warps: 2M x 4N), warp tile 64x32.
// smem: A stages [0, 3*10240)B, B stages [30720, 61440)B; row stride 40 bf16.
// ---------------------------------------------------------------------------
#define GSMEM 61440

template<int MODE>
__global__ __launch_bounds__(256)
void gemm_bf16(const float* __restrict__ bias,
               const float* __restrict__ shortcut,
               float* __restrict__ out)
{
    extern __shared__ bf16 dsm[];
    __shared__ float sred[512];
    const uint32_t smA = smem_u32(dsm);
    const uint32_t smB = smA + 30720;

    const int tid   = threadIdx.x;
    const int lane  = tid & 31;
    const int wid   = tid >> 5;
    const int warpM = wid >> 2;
    const int warpN = wid & 3;
    const int g     = lane >> 2;
    const int t2    = (lane & 3) * 2;
    const int lr    = lane & 15;       // ldmatrix row within 16
    const int lc    = lane >> 4;       // ldmatrix k-half
    const int bm    = blockIdx.y * 128;
    const int bn    = blockIdx.x * 128;

    const bf16* A = (MODE == 0) ? g_qbf : (MODE == 1) ? g_kvbf : g_xm;
    const bf16* W = (MODE == 0) ? g_wq  : (MODE == 1) ? g_wkv  : g_wm;
    const bf16* Ab = A + (size_t)bm * CDIM;
    const bf16* Wb = W + (size_t)bn * CDIM;

    // per-lane ldmatrix base offsets (within a stage)
    const uint32_t aoff = (uint32_t)((warpM * 64 + lr) * 80 + lc * 16);
    const uint32_t boff = (uint32_t)((warpN * 32 + lr) * 80 + lc * 16);

    auto load_tile = [&](int t) {
        const int kt = t * 32;
        const int stage = t % 3;
        const uint32_t ab = smA + stage * 10240;
        const uint32_t bb = smB + stage * 10240;
        #pragma unroll
        for (int it = 0; it < 2; it++) {
            int c   = tid + it * 256;      // 0..511
            int row = c >> 2;
            int cc  = c & 3;               // 16B chunk in row
            cp_async16(ab + row * 80 + cc * 16, Ab + (size_t)row * CDIM + kt + cc * 8);
            cp_async16(bb + row * 80 + cc * 16, Wb + (size_t)row * CDIM + kt + cc * 8);
        }
    };

    float acc[4][4][4] = {};

    load_tile(0); cp_commit();
    load_tile(1); cp_commit();

    for (int t = 0; t < 16; t++) {
        cp_wait<1>();
        __syncthreads();
        if (t + 2 < 16) load_tile(t + 2);
        cp_commit();

        const uint32_t sa = smA + (t % 3) * 10240;
        const uint32_t sb = smB + (t % 3) * 10240;
        #pragma unroll
        for (int ks = 0; ks < 2; ks++) {
            const int ko2 = ks * 32;   // ko * 2 bytes
            unsigned af[4][4], bfm[2][4];
            #pragma unroll
            for (int ma = 0; ma < 4; ma++)
                ldm_x4(af[ma], sa + aoff + ma * 16 * 80 + ko2);
            #pragma unroll
            for (int p = 0; p < 2; p++)
                ldm_x4(bfm[p], sb + boff + p * 16 * 80 + ko2);
            #pragma unroll
            for (int ma = 0; ma < 4; ma++)
                #pragma unroll
                for (int nb = 0; nb < 4; nb++)
                    mma16816(acc[ma][nb], af[ma],
                             bfm[nb >> 1][nb & 1], bfm[nb >> 1][2 + (nb & 1)]);
        }
    }

    // bias add
    float2 bv[4];
    #pragma unroll
    for (int nb = 0; nb < 4; nb++)
        bv[nb] = *(const float2*)&bias[bn + warpN * 32 + nb * 8 + t2];
    #pragma unroll
    for (int ma = 0; ma < 4; ma++)
        #pragma unroll
        for (int nb = 0; nb < 4; nb++) {
            acc[ma][nb][0] += bv[nb].x; acc[ma][nb][1] += bv[nb].y;
            acc[ma][nb][2] += bv[nb].x; acc[ma][nb][3] += bv[nb].y;
        }

    if (MODE == 2) {
        #pragma unroll
        for (int ma = 0; ma < 4; ma++)
            #pragma unroll
            for (int h2 = 0; h2 < 2; h2++) {
                int m = bm + warpM * 64 + ma * 16 + h2 * 8 + g;
                #pragma unroll
                for (int nb = 0; nb < 4; nb++) {
                    int n = bn + warpN * 32 + nb * 8 + t2;
                    float2 s = *(const float2*)&shortcut[(size_t)m * CDIM + n];
                    float2 o;
                    o.x = acc[ma][nb][h2 * 2 + 0] + s.x;
                    o.y = acc[ma][nb][h2 * 2 + 1] + s.y;
                    *(float2*)&out[(size_t)m * CDIM + n] = o;
                }
            }
    } else {
        float ssq[4][2];
        #pragma unroll
        for (int ma = 0; ma < 4; ma++)
            #pragma unroll
            for (int h2 = 0; h2 < 2; h2++) {
                float s = 0.f;
                #pragma unroll
                for (int nb = 0; nb < 4; nb++) {
                    float x = acc[ma][nb][h2 * 2], y = acc[ma][nb][h2 * 2 + 1];
                    s += x * x + y * y;
                }
                s += __shfl_xor_sync(0xffffffffu, s, 1);
                s += __shfl_xor_sync(0xffffffffu, s, 2);
                ssq[ma][h2] = s;
            }
        __syncthreads();
        if ((lane & 3) == 0) {
            #pragma unroll
            for (int ma = 0; ma < 4; ma++)
                #pragma unroll
                for (int h2 = 0; h2 < 2; h2++)
                    sred[wid * 64 + ma * 16 + h2 * 8 + g] = ssq[ma][h2];
        }
        __syncthreads();
        #pragma unroll
        for (int ma = 0; ma < 4; ma++)
            #pragma unroll
            for (int h2 = 0; h2 < 2; h2++) {
                int r = ma * 16 + h2 * 8 + g;
                float tot = sred[(wid & ~1) * 64 + r] + sred[((wid & ~1) + 1) * 64 + r];
                float rn = 1.f / fmaxf(sqrtf(tot), 1e-12f);
                int m = bm + warpM * 64 + r;
                #pragma unroll
                for (int nb = 0; nb < 4; nb++) {
                    int n = bn + warpN * 32 + nb * 8 + t2;
                    float v0 = acc[ma][nb][h2 * 2] * rn;
                    float v1 = acc[ma][nb][h2 * 2 + 1] * rn;
                    if (MODE == 0) {
                        int bt = m >> 8, lq = m & 255;
                        int h = n >> 6, d = n & 63;
                        *(unsigned*)&g_qh[(((size_t)(bt * 8 + h)) * 256 + lq) * 64 + d] = pk(v0, v1);
                    } else {
                        int bt = m >> 9, lk = m & 511;
                        if (n < 512) {
                            int h = n >> 6, d = n & 63;
                            *(unsigned*)&g_kh[(((size_t)(bt * 8 + h)) * 512 + lk) * 64 + d] = pk(v0, v1);
                        } else {
                            int h = (n >> 6) - 8, d = n & 63;
                            size_t base = (((size_t)(bt * 8 + h)) * 64);
                            g_vt[(base + d)     * 512 + lk] = __float2bfloat16(v0);
                            g_vt[(base + d + 1) * 512 + lk] = __float2bfloat16(v1);
                        }
                    }
                }
            }
    }
}

// ---------------------------------------------------------------------------
// Attention, 3-stage cp.async on K/V + ldmatrix fragments.
// block = (128 q-rows, h, bt), 8 warps.
// dyn smem: Qs[128*72] | Ks[3][64*72] | Vs[3][64*72]  = 73728 B
// ---------------------------------------------------------------------------
#define ASMEM 73728

__global__ __launch_bounds__(256)
void attn_bf16()
{
    extern __shared__ bf16 dsm[];
    bf16* Qs = dsm;                       // 9216 elems
    const uint32_t smQ = smem_u32(dsm);
    const uint32_t smK = smQ + 9216 * 2;
    const uint32_t smV = smK + 13824 * 2;

    const int tid  = threadIdx.x;
    const int lane = tid & 31;
    const int wid  = tid >> 5;
    const int g    = lane >> 2;
    const int t2   = (lane & 3) * 2;
    const int lr   = lane & 15;
    const int lc   = lane >> 4;
    const int qt   = blockIdx.x;
    const int h    = blockIdx.y;
    const int bt   = blockIdx.z;

    const bf16* Qg = g_qh + (((size_t)(bt * 8 + h)) * 256 + qt * 128) * 64;
    const bf16* Kg = g_kh + ((size_t)(bt * 8 + h)) * 512 * 64;
    const bf16* Vg = g_vt + ((size_t)(bt * 8 + h)) * 64 * 512;

    auto load_kv = [&](int t) {
        const int stage = t % 3;
        const uint32_t kb = smK + stage * 4608 * 2;
        const uint32_t vb = smV + stage * 4608 * 2;
        #pragma unroll
        for (int it = 0; it < 2; it++) {
            int c   = tid + it * 256;     // 0..511
            int row = c >> 3;
            int cc  = c & 7;              // 16B chunk
            cp_async16(kb + row * 144 + cc * 16, Kg + (size_t)(t * 64 + row) * 64 + cc * 8);
            cp_async16(vb + row * 144 + cc * 16, Vg + (size_t)row * 512 + t * 64 + cc * 8);
        }
    };

    load_kv(0); cp_commit();
    load_kv(1); cp_commit();

    // Q tile 128x64 -> smem (plain)
    #pragma unroll
    for (int it = 0; it < 4; it++) {
        int idx = tid + it * 256;
        int row = idx >> 3, c = (idx & 7) * 8;
        *(uint4*)&Qs[row * 72 + c] = *(const uint4*)&Qg[(size_t)row * 64 + c];
    }
    __syncthreads();

    // preload Q fragments via ldmatrix
    unsigned qf[4][4];
    {
        const uint32_t qoff = smQ + (uint32_t)((wid * 16 + lr) * 144 + lc * 16);
        #pragma unroll
        for (int ka = 0; ka < 4; ka++)
            ldm_x4(qf[ka], qoff + ka * 32);
    }

    // per-lane ldmatrix offsets for K/V tiles (row stride 144B)
    const uint32_t nvoff = (uint32_t)(lr * 144 + lc * 16);

    float oacc[8][4] = {};
    float lsum0 = 0.f, lsum1 = 0.f;
    const float sc = 0.125f * 1.4426950408889634f;

    for (int t = 0; t < 8; t++) {
        cp_wait<1>();
        __syncthreads();
        if (t + 2 < 8) load_kv(t + 2);
        cp_commit();

        const uint32_t kb = smK + (t % 3) * 4608 * 2;
        const uint32_t vb = smV + (t % 3) * 4608 * 2;

        // S = Q K^T
        float sacc[8][4] = {};
        #pragma unroll
        for (int ka = 0; ka < 4; ka++) {
            #pragma unroll
            for (int p = 0; p < 4; p++) {
                unsigned kf[4];
                ldm_x4(kf, kb + nvoff + p * 16 * 144 + ka * 32);
                mma16816(sacc[2 * p + 0], qf[ka], kf[0], kf[2]);
                mma16816(sacc[2 * p + 1], qf[ka], kf[1], kf[3]);
            }
        }

        // exp (bounded arg), accumulate row sums
        #pragma unroll
        for (int nb = 0; nb < 8; nb++) {
            #pragma unroll
            for (int i = 0; i < 4; i++) {
                float e;
                asm("ex2.approx.f32 %0, %1;" : "=f"(e) : "f"(sacc[nb][i] * sc));
                sacc[nb][i] = e;
            }
            lsum0 += sacc[nb][0] + sacc[nb][1];
            lsum1 += sacc[nb][2] + sacc[nb][3];
        }

        // O += P V
        #pragma unroll
        for (int kk = 0; kk < 4; kk++) {
            unsigned pf[4];
            pf[0] = pk(sacc[2 * kk][0],     sacc[2 * kk][1]);
            pf[1] = pk(sacc[2 * kk][2],     sacc[2 * kk][3]);
            pf[2] = pk(sacc[2 * kk + 1][0], sacc[2 * kk + 1][1]);
            pf[3] = pk(sacc[2 * kk + 1][2], sacc[2 * kk + 1][3]);
            #pragma unroll
            for (int p = 0; p < 4; p++) {
                unsigned vf[4];
                ldm_x4(vf, vb + nvoff + p * 16 * 144 + kk * 32);
                mma16816(oacc[2 * p + 0], pf, vf[0], vf[2]);
                mma16816(oacc[2 * p + 1], pf, vf[1], vf[3]);
            }
        }
    }

    lsum0 += __shfl_xor_sync(0xffffffffu, lsum0, 1);
    lsum0 += __shfl_xor_sync(0xffffffffu, lsum0, 2);
    lsum1 += __shfl_xor_sync(0xffffffffu, lsum1, 1);
    lsum1 += __shfl_xor_sync(0xffffffffu, lsum1, 2);
    const float rl0 = 1.f / lsum0, rl1 = 1.f / lsum1;

    bf16* Og = g_xm + ((size_t)bt * 256 + qt * 128) * 512 + h * 64;
    const int r0 = wid * 16 + g;
    #pragma unroll
    for (int nb = 0; nb < 8; nb++) {
        int n = nb * 8 + t2;
        *(unsigned*)&Og[(size_t)r0 * 512 + n]       = pk(oacc[nb][0] * rl0, oacc[nb][1] * rl0);
        *(unsigned*)&Og[(size_t)(r0 + 8) * 512 + n] = pk(oacc[nb][2] * rl1, oacc[nb][3] * rl1);
    }
}

// ---------------------------------------------------------------------------
extern "C" void kernel_launch(void* const* d_in, const int* in_sizes, int n_in,
                              void* d_out, int out_size)
{
    const float* q   = (const float*)d_in[0];
    const float* kv  = (const float*)d_in[1];
    const float* Wq  = (const float*)d_in[2];
    const float* bq  = (const float*)d_in[3];
    const float* Wkv = (const float*)d_in[4];
    const float* bkv = (const float*)d_in[5];
    const float* Wm  = (const float*)d_in[6];
    const float* bm  = (const float*)d_in[7];
    float* out = (float*)d_out;

    cudaFuncSetAttribute(gemm_bf16<0>, cudaFuncAttributeMaxDynamicSharedMemorySize, GSMEM);
    cudaFuncSetAttribute(gemm_bf16<1>, cudaFuncAttributeMaxDynamicSharedMemorySize, GSMEM);
    cudaFuncSetAttribute(gemm_bf16<2>, cudaFuncAttributeMaxDynamicSharedMemorySize, GSMEM);
    cudaFuncSetAttribute(attn_bf16,    cudaFuncAttributeMaxDynamicSharedMemorySize, ASMEM);

    convert_inputs <<<(Q8 + KV8) / 256, 256>>>(q, kv);
    convert_weights<<<(WQ8 + WKV8 + WM8) / 256, 256>>>(Wq, Wkv, Wm);

    gemm_bf16<0><<<dim3(4, 128), 256, GSMEM>>>(bq, nullptr, nullptr);
    gemm_bf16<1><<<dim3(8, 256), 256, GSMEM>>>(bkv, nullptr, nullptr);
    attn_bf16<<<dim3(2, 8, 64), 256, ASMEM>>>();
    gemm_bf16<2><<<dim3(4, 128), 256, GSMEM>>>(bm, q, out);
}